// round 15
// baseline (speedup 1.0000x reference)
#include <cuda_runtime.h>
#include <math.h>

#define BB 16384
#define DD 3072
#define HH 128
#define OO 10
#define EE 8

// Scratch (allocation-free rule: __device__ globals)
__device__ int   g_counts[EE];
__device__ int   g_tok[EE * BB];
__device__ float g_wgt[EE * BB];

// ---------------------------------------------------------------------------
// Kernel 0: zero output + per-expert counters (graph replays re-run this)
// ---------------------------------------------------------------------------
__global__ void zero_kernel(float* __restrict__ y) {
    int i = blockIdx.x * 256 + threadIdx.x;
    if (i < BB * OO) y[i] = 0.0f;
    if (i < EE) g_counts[i] = 0;
}

// ---------------------------------------------------------------------------
// Kernel 1: gate — one warp per token.
// scores = x @ gate_w + gate_b ; top-2 ; weights exactly per reference:
//   q = softmax(scores); w_k = q_k / (q_top0 + q_top1 + 1e-8)
// Appends (token, weight) to the chosen experts' lists.
// ---------------------------------------------------------------------------
__global__ void gate_kernel(const float* __restrict__ x,
                            const float* __restrict__ gw,
                            const float* __restrict__ gb) {
    int gid  = blockIdx.x * blockDim.x + threadIdx.x;
    int b    = gid >> 5;
    int lane = gid & 31;
    if (b >= BB) return;

    const float* xr = x + (size_t)b * DD;
    float acc[EE] = {0.f, 0.f, 0.f, 0.f, 0.f, 0.f, 0.f, 0.f};

    for (int d = lane; d < DD; d += 32) {
        float  xv = __ldg(xr + d);
        float4 g0 = *(const float4*)(gw + (size_t)d * EE);
        float4 g1 = *(const float4*)(gw + (size_t)d * EE + 4);
        acc[0] += xv * g0.x; acc[1] += xv * g0.y;
        acc[2] += xv * g0.z; acc[3] += xv * g0.w;
        acc[4] += xv * g1.x; acc[5] += xv * g1.y;
        acc[6] += xv * g1.z; acc[7] += xv * g1.w;
    }
#pragma unroll
    for (int off = 16; off > 0; off >>= 1) {
#pragma unroll
        for (int e = 0; e < EE; e++)
            acc[e] += __shfl_xor_sync(0xffffffffu, acc[e], off);
    }

    if (lane == 0) {
        float s[EE], p[EE];
        float m = -INFINITY;
#pragma unroll
        for (int e = 0; e < EE; e++) { s[e] = acc[e] + gb[e]; m = fmaxf(m, s[e]); }
        float Z = 0.f;
#pragma unroll
        for (int e = 0; e < EE; e++) { p[e] = expf(s[e] - m); Z += p[e]; }

        // top-2 (ties -> lowest index, matching jax top_k)
        int i0 = 0; float b0 = s[0];
#pragma unroll
        for (int e = 1; e < EE; e++) if (s[e] > b0) { b0 = s[e]; i0 = e; }
        int i1 = -1; float b1v = -INFINITY;
#pragma unroll
        for (int e = 0; e < EE; e++)
            if (e != i0 && s[e] > b1v) { b1v = s[e]; i1 = e; }

        float q0 = p[i0] / Z;
        float q1 = p[i1] / Z;
        float dn = q0 + q1 + 1e-8f;
        float w0 = q0 / dn;
        float w1 = q1 / dn;

        int pos0 = atomicAdd(&g_counts[i0], 1);
        g_tok[i0 * BB + pos0] = b;
        g_wgt[i0 * BB + pos0] = w0;
        int pos1 = atomicAdd(&g_counts[i1], 1);
        g_tok[i1 * BB + pos1] = b;
        g_wgt[i1 * BB + pos1] = w1;
    }
}

// ---------------------------------------------------------------------------
// Kernel 2: grouped expert FFN.
// grid = (128 tiles, 8 experts); block = 256 threads (16x16, 8x8 micro-tile).
// GEMM1: h1[128x128] = relu(gather(x)[128x3072] @ w1[e] + b1)   (smem staged)
// GEMM2: h2[128x128] = relu(h1 @ w2[e] + b2)
// GEMM3: y[tok, :10] += wgt * (h2 @ w3[e] + b3)   (atomicAdd, 2 adds/elem)
// Shared memory: tok/wgt (1KB) + Xs (16KB) + Ws (16KB) + Hs (64KB) = 97KB
// Hs holds h1 (transposed [h][r]) during GEMM2, then is overwritten by h2.
// ---------------------------------------------------------------------------
#define SMEM_FLOATS (256 + 4096 + 4096 + 16384)
#define SMEM_BYTES  (SMEM_FLOATS * 4)

__global__ void expert_kernel(const float* __restrict__ x,
                              const float* __restrict__ w1,
                              const float* __restrict__ b1,
                              const float* __restrict__ w2,
                              const float* __restrict__ b2,
                              const float* __restrict__ w3,
                              const float* __restrict__ b3,
                              float* __restrict__ y) {
    extern __shared__ float sm[];
    int*   sTok = (int*)sm;        // [128]
    float* sWgt = sm + 128;        // [128]
    float* Xs   = sm + 256;        // [32][128]
    float* Ws   = sm + 256 + 4096; // [32][128]
    float* Hs   = sm + 256 + 8192; // [128][128] (transposed: Hs[h][r])

    const int e    = blockIdx.y;
    const int cnt  = g_counts[e];
    const int base = blockIdx.x * 128;
    if (base >= cnt) return;
    const int rows = min(128, cnt - base);

    const int tid = threadIdx.x;
    const int tx  = tid & 15;   // col group
    const int ty  = tid >> 4;   // row group

    if (tid < 128) {
        int src   = base + min(tid, rows - 1);  // clamp (garbage rows masked later)
        sTok[tid] = g_tok[e * BB + src];
        sWgt[tid] = (tid < rows) ? g_wgt[e * BB + src] : 0.f;
    }
    __syncthreads();

    // ---------------- GEMM1: K = 3072 ----------------
    float acc[8][8];
#pragma unroll
    for (int i = 0; i < 8; i++)
#pragma unroll
        for (int j = 0; j < 8; j++) acc[i][j] = 0.f;

    const float* w1e = w1 + (size_t)e * DD * HH;

    for (int k0 = 0; k0 < DD; k0 += 32) {
        // stage: Xs[kk][row] = x[tok[row]][k0+kk]  (gathered, transposed)
        //        Ws[kk][h]   = w1[e][k0+kk][h]     (contiguous copy)
        const float4* wsrc = (const float4*)(w1e + (size_t)k0 * HH);
#pragma unroll
        for (int i = 0; i < 4; i++) {
            int idx4 = tid + i * 256;          // 0..1023
            int row  = idx4 >> 3;              // 8 float4 per row
            int c4   = idx4 & 7;
            float4 v = *(const float4*)(x + (size_t)sTok[row] * DD + k0 + c4 * 4);
            int kk = c4 * 4;
            Xs[(kk + 0) * 128 + row] = v.x;
            Xs[(kk + 1) * 128 + row] = v.y;
            Xs[(kk + 2) * 128 + row] = v.z;
            Xs[(kk + 3) * 128 + row] = v.w;
            ((float4*)Ws)[idx4] = wsrc[idx4];
        }
        __syncthreads();

#pragma unroll
        for (int kk = 0; kk < 32; kk++) {
            float a[8], bv[8];
            *(float4*)(a)      = *(float4*)&Xs[kk * 128 + ty * 8];
            *(float4*)(a + 4)  = *(float4*)&Xs[kk * 128 + ty * 8 + 4];
            *(float4*)(bv)     = *(float4*)&Ws[kk * 128 + tx * 8];
            *(float4*)(bv + 4) = *(float4*)&Ws[kk * 128 + tx * 8 + 4];
#pragma unroll
            for (int i = 0; i < 8; i++)
#pragma unroll
                for (int j = 0; j < 8; j++)
                    acc[i][j] += a[i] * bv[j];
        }
        __syncthreads();
    }

    // bias + relu -> Hs transposed (Hs[h][r] = h1[r][h])
#pragma unroll
    for (int j = 0; j < 8; j++) {
        int   c  = tx * 8 + j;
        float bj = b1[e * HH + c];
#pragma unroll
        for (int i = 0; i < 8; i++) {
            int r = ty * 8 + i;
            Hs[c * 128 + r] = fmaxf(acc[i][j] + bj, 0.f);
        }
    }
    __syncthreads();

    // ---------------- GEMM2: K = 128 ----------------
    float acc2[8][8];
#pragma unroll
    for (int i = 0; i < 8; i++)
#pragma unroll
        for (int j = 0; j < 8; j++) acc2[i][j] = 0.f;

    const float* w2e = w2 + (size_t)e * HH * HH;
    for (int k0 = 0; k0 < HH; k0 += 32) {
        const float4* wsrc = (const float4*)(w2e + (size_t)k0 * HH);
#pragma unroll
        for (int i = 0; i < 4; i++) {
            int idx4 = tid + i * 256;
            ((float4*)Ws)[idx4] = wsrc[idx4];
        }
        __syncthreads();

#pragma unroll
        for (int kk = 0; kk < 32; kk++) {
            float a[8], bv[8];
            *(float4*)(a)      = *(float4*)&Hs[(k0 + kk) * 128 + ty * 8];
            *(float4*)(a + 4)  = *(float4*)&Hs[(k0 + kk) * 128 + ty * 8 + 4];
            *(float4*)(bv)     = *(float4*)&Ws[kk * 128 + tx * 8];
            *(float4*)(bv + 4) = *(float4*)&Ws[kk * 128 + tx * 8 + 4];
#pragma unroll
            for (int i = 0; i < 8; i++)
#pragma unroll
                for (int j = 0; j < 8; j++)
                    acc2[i][j] += a[i] * bv[j];
        }
        __syncthreads();  // also guarantees all h1 reads done before overwrite
    }

    // bias + relu -> Hs overwritten with h2 (transposed)
#pragma unroll
    for (int j = 0; j < 8; j++) {
        int   c  = tx * 8 + j;
        float bj = b2[e * HH + c];
#pragma unroll
        for (int i = 0; i < 8; i++) {
            int r = ty * 8 + i;
            Hs[c * 128 + r] = fmaxf(acc2[i][j] + bj, 0.f);
        }
    }
    __syncthreads();

    // ---------------- GEMM3 + weighted scatter ----------------
    const float* w3e = w3 + (size_t)e * HH * OO;
    const float* b3e = b3 + e * OO;
    for (int idx = tid; idx < 128 * OO; idx += 256) {
        int r = idx / OO;
        int o = idx - r * OO;
        if (r >= rows) continue;
        float sacc = b3e[o];
#pragma unroll 8
        for (int h = 0; h < HH; h++)
            sacc += Hs[h * 128 + r] * w3e[h * OO + o];
        atomicAdd(&y[(size_t)sTok[r] * OO + o], sWgt[r] * sacc);
    }
}

// ---------------------------------------------------------------------------
extern "C" void kernel_launch(void* const* d_in, const int* in_sizes, int n_in,
                              void* d_out, int out_size) {
    const float* x  = (const float*)d_in[0];
    const float* gw = (const float*)d_in[1];
    const float* gb = (const float*)d_in[2];
    const float* w1 = (const float*)d_in[3];
    const float* b1 = (const float*)d_in[4];
    const float* w2 = (const float*)d_in[5];
    const float* b2 = (const float*)d_in[6];
    const float* w3 = (const float*)d_in[7];
    const float* b3 = (const float*)d_in[8];
    float* y = (float*)d_out;

    cudaFuncSetAttribute(expert_kernel,
                         cudaFuncAttributeMaxDynamicSharedMemorySize, SMEM_BYTES);

    zero_kernel<<<(BB * OO + 255) / 256, 256>>>(y);
    gate_kernel<<<BB / 8, 256>>>(x, gw, gb);
    expert_kernel<<<dim3(128, EE), 256, SMEM_BYTES>>>(x, w1, b1, w2, b2, w3, b3, y);
}